// round 12
// baseline (speedup 1.0000x reference)
#include <cuda_runtime.h>
#include <math.h>
#include <stdint.h>

// Problem constants
#define SQ    1024      // sequence length
#define DM    512       // model dim
#define NH    8         // heads
#define HDIM  64        // head dim
#define NLAY  4         // layers
#define QK_SCALE 0.125f // 1/sqrt(64)

// ---------------------------------------------------------------------------
// Scratch (no allocations allowed -> __device__ globals)
// ---------------------------------------------------------------------------
__device__ float g_h [SQ*DM];
__device__ float g_n [SQ*DM];
__device__ float g_q [SQ*DM];
__device__ float g_kh[SQ*DM];
__device__ float g_kl[SQ*DM];
__device__ float g_vh[SQ*DM];
__device__ float g_vl[SQ*DM];
__device__ float g_ao[SQ*DM];
__device__ float g_f1[SQ*2048];
__device__ float g_fi[SQ*1024];

// pre-split weight store (tf32 hi/lo), all tensors concatenated (floats):
#define OFF_EMB 0
#define OFF_WQ  65536
#define OFF_WK  1114112
#define OFF_WV  2162688
#define OFF_WO  3211264
#define OFF_W1  4259840
#define OFF_W2  8454144
#define OFF_WI  12648448
#define OFF_WF  13172736
#define WTOT    13572096
__device__ float g_wh[WTOT];
__device__ float g_wl[WTOT];
__device__ float g_erh[NLAY*2047*HDIM];
__device__ float g_erl[NLAY*2047*HDIM];

__device__ __forceinline__ float gelu_f(float x){
    return 0.5f*x*(1.f + erff(x*0.7071067811865476f));
}

__device__ __forceinline__ uint32_t f2tf(float x){
    uint32_t u; asm("cvt.rna.tf32.f32 %0, %1;" : "=r"(u) : "f"(x)); return u;
}
__device__ __forceinline__ void split_tf(float x, uint32_t& hi, uint32_t& lo){
    hi = f2tf(x);
    lo = f2tf(x - __uint_as_float(hi));
}

__device__ __forceinline__ void mma_tf32(float c[4],
    uint32_t a0, uint32_t a1, uint32_t a2, uint32_t a3,
    uint32_t b0, uint32_t b1)
{
    asm volatile(
        "mma.sync.aligned.m16n8k8.row.col.f32.tf32.tf32.f32 "
        "{%0,%1,%2,%3}, {%4,%5,%6,%7}, {%8,%9}, {%0,%1,%2,%3};"
        : "+f"(c[0]), "+f"(c[1]), "+f"(c[2]), "+f"(c[3])
        : "r"(a0), "r"(a1), "r"(a2), "r"(a3), "r"(b0), "r"(b1));
}

__device__ __forceinline__ void cp16(uint32_t smem_dst, const void* gsrc){
    asm volatile("cp.async.cg.shared.global [%0], [%1], 16;\n"
                 :: "r"(smem_dst), "l"(gsrc));
}
// predicate-off: size 0 AND clamped (valid) source address -> never OOB
__device__ __forceinline__ void cp4z(uint32_t smem_dst, const void* gsrc, bool pred){
    int sz = pred ? 4 : 0;
    asm volatile("cp.async.ca.shared.global [%0], [%1], 4, %2;\n"
                 :: "r"(smem_dst), "l"(gsrc), "r"(sz));
}
__device__ __forceinline__ void cp_commit(){
    asm volatile("cp.async.commit_group;\n" ::: "memory");
}

// ---------------------------------------------------------------------------
// Fused weight pre-split: all tensors in ONE launch. grid (4096, NSEG).
// ---------------------------------------------------------------------------
#define NSEG 10
struct WsegArgs {
    const float4* src[NSEG];
    float4* dh[NSEG];
    float4* dl[NSEG];
    int n4[NSEG];
};

__global__ __launch_bounds__(256) void wsplit_all_k(WsegArgs a)
{
    const int seg = blockIdx.y;
    const int i = blockIdx.x*256 + threadIdx.x;
    if (i < a.n4[seg]){
        float4 v = a.src[seg][i];
        float xs[4] = {v.x, v.y, v.z, v.w};
        float hs[4], ls[4];
        #pragma unroll
        for (int j = 0; j < 4; j++){
            uint32_t h, l; split_tf(xs[j], h, l);
            hs[j] = __uint_as_float(h); ls[j] = __uint_as_float(l);
        }
        a.dh[seg][i] = make_float4(hs[0],hs[1],hs[2],hs[3]);
        a.dl[seg][i] = make_float4(ls[0],ls[1],ls[2],ls[3]);
    }
}

// ---------------------------------------------------------------------------
// 3xTF32 tensor-core GEMM, cp.async 3-stage pipeline, PRE-SPLIT B (weights).
// EPI: 0 = bias, 1 = bias+gelu, 2 = bias+residual-add,
//      3 = bias + tf32-split output (C=hi array, C2=lo array)
// ---------------------------------------------------------------------------
template<int EPI>
__device__ __forceinline__ void gemm_core(
    const float* __restrict__ A, int lda,
    const float* __restrict__ Bh, const float* __restrict__ Bl, int ldb,
    float* __restrict__ C, float* __restrict__ C2, int ldc,
    const float* __restrict__ bias,
    const float* __restrict__ res,
    int M, int N, int K, int row0, int col0)
{
    constexpr int ST = 3;
    __shared__ float As [ST][64*20];   // raw A,  [m][k] stride 20
    __shared__ float BhS[ST][16*72];   // tf32-hi B, [k][n] stride 72
    __shared__ float BlS[ST][16*72];   // tf32-lo B

    const int tid  = threadIdx.x;
    const int lane = tid & 31;
    const int w    = tid >> 5;
    const int wm   = w & 3;
    const int wn   = w >> 2;
    const int g    = lane >> 2;
    const int t    = lane & 3;

    float acc[4][4] = {};

    const int ar  = tid >> 2;
    const int ac4 = (tid & 3) * 4;
    const float* Aptr = A + (long)(row0+ar)*lda + ac4;

    const int br  = tid >> 4;
    const int bc4 = (tid & 15) * 4;
    const bool vecB = ((ldb & 3) == 0) && (col0 + 64 <= N);
    const float* Bvh = Bh + (long)br*ldb + col0 + bc4;
    const float* Bvl = Bl + (long)br*ldb + col0 + bc4;
    int sr[4], scc[4]; bool sp[4];
    if (!vecB){
        #pragma unroll
        for (int j = 0; j < 4; j++){
            int idx = tid + j*256;
            sr[j] = idx >> 6; scc[j] = idx & 63;
            sp[j] = (col0 + scc[j]) < N;
        }
    }

    const int ntiles = K >> 4;

    auto issue = [&](int k0, int s){
        cp16((uint32_t)__cvta_generic_to_shared(&As[s][ar*20 + ac4]), Aptr + k0);
        if (vecB){
            cp16((uint32_t)__cvta_generic_to_shared(&BhS[s][br*72 + bc4]),
                 Bvh + (long)k0*ldb);
            cp16((uint32_t)__cvta_generic_to_shared(&BlS[s][br*72 + bc4]),
                 Bvl + (long)k0*ldb);
        } else {
            #pragma unroll
            for (int j = 0; j < 4; j++){
                long go = (long)(k0+sr[j])*ldb + col0 + scc[j];
                cp4z((uint32_t)__cvta_generic_to_shared(&BhS[s][sr[j]*72 + scc[j]]),
                     sp[j] ? (Bh + go) : Bh, sp[j]);
                cp4z((uint32_t)__cvta_generic_to_shared(&BlS[s][sr[j]*72 + scc[j]]),
                     sp[j] ? (Bl + go) : Bl, sp[j]);
            }
        }
        cp_commit();
    };

    issue(0, 0); issue(16, 1);

    const int mA0 = (wm*16 + g)*20;
    const int mA1 = (wm*16 + g + 8)*20;

    int s = 0;
    for (int kt = 0; kt < ntiles; kt++){
        if (kt + 1 < ntiles) asm volatile("cp.async.wait_group 1;\n" ::: "memory");
        else                 asm volatile("cp.async.wait_group 0;\n" ::: "memory");
        __syncthreads();

        int nx = kt + 2;
        if (nx < ntiles){
            int sn = s + 2; if (sn >= ST) sn -= ST;
            issue(nx*16, sn);
        }

        const float* Asl = As[s];
        const float* Bhl = BhS[s];
        const float* Bll = BlS[s];

        #pragma unroll
        for (int ks = 0; ks < 16; ks += 8){
            float a0 = Asl[mA0 + ks + t    ];
            float a1 = Asl[mA1 + ks + t    ];
            float a2 = Asl[mA0 + ks + t + 4];
            float a3 = Asl[mA1 + ks + t + 4];
            uint32_t ah0,al0,ah1,al1,ah2,al2,ah3,al3;
            split_tf(a0,ah0,al0); split_tf(a1,ah1,al1);
            split_tf(a2,ah2,al2); split_tf(a3,ah3,al3);
            #pragma unroll
            for (int nt = 0; nt < 4; nt++){
                int bn = wn*32 + nt*8 + g;
                uint32_t bh0 = __float_as_uint(Bhl[(ks + t    )*72 + bn]);
                uint32_t bh1 = __float_as_uint(Bhl[(ks + t + 4)*72 + bn]);
                uint32_t bl0 = __float_as_uint(Bll[(ks + t    )*72 + bn]);
                uint32_t bl1 = __float_as_uint(Bll[(ks + t + 4)*72 + bn]);
                mma_tf32(acc[nt], ah0, ah1, ah2, ah3, bh0, bh1);
                mma_tf32(acc[nt], ah0, ah1, ah2, ah3, bl0, bl1);
                mma_tf32(acc[nt], al0, al1, al2, al3, bh0, bh1);
            }
        }
        if (++s >= ST) s -= ST;
    }

    const int r0 = row0 + wm*16 + g;
    const int r1 = r0 + 8;
    #pragma unroll
    for (int nt = 0; nt < 4; nt++){
        int col = col0 + wn*32 + nt*8 + 2*t;
        #pragma unroll
        for (int j = 0; j < 2; j++){
            int c = col + j;
            if (c < N){
                float v0 = acc[nt][j];
                float v1 = acc[nt][2+j];
                if (bias){ float bb = bias[c]; v0 += bb; v1 += bb; }
                if (EPI == 1){ v0 = gelu_f(v0); v1 = gelu_f(v1); }
                if (EPI == 2){
                    v0 += res[(long)r0*ldc + c];
                    v1 += res[(long)r1*ldc + c];
                }
                if (EPI == 3){
                    uint32_t hh, ll;
                    split_tf(v0, hh, ll);
                    C [(long)r0*ldc + c] = __uint_as_float(hh);
                    C2[(long)r0*ldc + c] = __uint_as_float(ll);
                    split_tf(v1, hh, ll);
                    C [(long)r1*ldc + c] = __uint_as_float(hh);
                    C2[(long)r1*ldc + c] = __uint_as_float(ll);
                } else {
                    C[(long)r0*ldc + c] = v0;
                    C[(long)r1*ldc + c] = v1;
                }
            }
        }
    }
}

template<int EPI>
__global__ __launch_bounds__(256) void gemm_tc(
    const float* __restrict__ A, int lda,
    const float* __restrict__ Bh, const float* __restrict__ Bl, int ldb,
    float* __restrict__ C, int ldc,
    const float* __restrict__ bias,
    const float* __restrict__ res,
    int M, int N, int K)
{
    gemm_core<EPI>(A, lda, Bh, Bl, ldb, C, nullptr, ldc, bias, res,
                   M, N, K, blockIdx.y*64, blockIdx.x*64);
}

// Fused QKV: z=0 -> raw q; z=1 -> split (kh,kl); z=2 -> split (vh,vl)
__global__ __launch_bounds__(256) void gemm_qkv(
    const float* __restrict__ n,
    const float* __restrict__ wh, const float* __restrict__ wl, // layer q-base
    const float* __restrict__ bq, const float* __restrict__ bk, const float* __restrict__ bv,
    float* __restrict__ q,
    float* __restrict__ kh, float* __restrict__ kl,
    float* __restrict__ vh, float* __restrict__ vl)
{
    const int z = blockIdx.z;
    const long dz = (long)z * (OFF_WK - OFF_WQ);
    const int row0 = blockIdx.y*64, col0 = blockIdx.x*64;
    if (z == 0)
        gemm_core<0>(n, DM, wh + dz, wl + dz, DM, q,  nullptr, DM, bq, nullptr,
                     SQ, DM, DM, row0, col0);
    else if (z == 1)
        gemm_core<3>(n, DM, wh + dz, wl + dz, DM, kh, kl,      DM, bk, nullptr,
                     SQ, DM, DM, row0, col0);
    else
        gemm_core<3>(n, DM, wh + dz, wl + dz, DM, vh, vl,      DM, bv, nullptr,
                     SQ, DM, DM, row0, col0);
}

// ---------------------------------------------------------------------------
// LayerNorm over D=512. One block (128 threads, 1 float4 each) per row.
// ---------------------------------------------------------------------------
__global__ __launch_bounds__(128) void ln_k(
    const float* __restrict__ x, const float* __restrict__ g,
    const float* __restrict__ b, float* __restrict__ y)
{
    const int row = blockIdx.x, tid = threadIdx.x;
    float4 v = reinterpret_cast<const float4*>(x + (long)row*DM)[tid];
    float s  = v.x+v.y+v.z+v.w;
    float s2 = v.x*v.x+v.y*v.y+v.z*v.z+v.w*v.w;
    #pragma unroll
    for (int o = 16; o; o >>= 1){
        s  += __shfl_xor_sync(0xffffffffu, s,  o);
        s2 += __shfl_xor_sync(0xffffffffu, s2, o);
    }
    __shared__ float sh[8];
    if ((tid & 31) == 0){ sh[tid>>5] = s; sh[4 + (tid>>5)] = s2; }
    __syncthreads();
    s  = sh[0]+sh[1]+sh[2]+sh[3];
    s2 = sh[4]+sh[5]+sh[6]+sh[7];
    const float m = s * (1.f/DM);
    const float rstd = rsqrtf(s2*(1.f/DM) - m*m + 1e-5f);
    float4 gg = reinterpret_cast<const float4*>(g)[tid];
    float4 bb = reinterpret_cast<const float4*>(b)[tid];
    float4 o;
    o.x = (v.x-m)*rstd*gg.x + bb.x;
    o.y = (v.y-m)*rstd*gg.y + bb.y;
    o.z = (v.z-m)*rstd*gg.z + bb.z;
    o.w = (v.w-m)*rstd*gg.w + bb.w;
    reinterpret_cast<float4*>(y + (long)row*DM)[tid] = o;
}

// ---------------------------------------------------------------------------
// Fused flash-style attention (R12): K, V, Er all pre-split in global.
// Single-buffered split K/E/V (same smem as double-buffered raw).
// Pipeline per iter: [S1: KE(i) ready] -> issue V(i) -> QK/QE mma -> S2 ->
//   issue KE(i+1) -> softmax -> wait V(i) -> S4 -> PV mma.
// ---------------------------------------------------------------------------
#define AQ_H   0
#define AQ_L   4352
#define AK_H   8704
#define AK_L   13056
#define AE_H   17408
#define AE_L   26112
#define AV_H   34816
#define AV_L   39424
#define AR     44032
#define AREDM  52736
#define AREDS  52864
#define ATT_FLOATS 52992
#define ATT_SMEM  (ATT_FLOATS*4)   // 211968 bytes

__global__ __launch_bounds__(256) void attn_k(
    const float* __restrict__ qg,
    const float* __restrict__ khg, const float* __restrict__ klg,
    const float* __restrict__ vhg, const float* __restrict__ vlg,
    const float* __restrict__ erh, const float* __restrict__ erl,
    float* __restrict__ ao)
{
    extern __shared__ float sm[];
    float* QH  = sm + AQ_H;      // [64][68]
    float* QL  = sm + AQ_L;
    float* KH  = sm + AK_H;      // [64][68]
    float* KL  = sm + AK_L;
    float* EH  = sm + AE_H;      // [128][68] (127 rows used)
    float* EL  = sm + AE_L;
    float* VH  = sm + AV_H;      // [64][72]
    float* VL  = sm + AV_L;
    float* RS  = sm + AR;        // [64][136]; PH/PL alias after S3
    float* PH  = sm + AR;        // [64][68]
    float* PL  = sm + AR + 4352;
    float* redm = sm + AREDM;    // [2][64]
    float* reds = sm + AREDS;    // [2][64]

    const int s0  = blockIdx.x * 64;
    const int h   = blockIdx.y;
    const int tid = threadIdx.x;
    const int lane = tid & 31, w = tid >> 5;
    const int wm = w & 3, wn = w >> 2;
    const int g = lane >> 2, t = lane & 3;

    // ---- load + pre-split Q tile (once)
    #pragma unroll
    for (int i = 0; i < 4; i++){
        int c = tid + i*256;
        int row = c >> 4, q4 = (c & 15) * 4;
        float4 v4 = *(const float4*)(qg + (long)(s0+row)*DM + h*HDIM + q4);
        float xs[4] = {v4.x, v4.y, v4.z, v4.w};
        #pragma unroll
        for (int j = 0; j < 4; j++){
            uint32_t hh, ll; split_tf(xs[j], hh, ll);
            QH[row*68 + q4 + j] = __uint_as_float(hh);
            QL[row*68 + q4 + j] = __uint_as_float(ll);
        }
    }

    auto issue_ke = [&](int t0){
        #pragma unroll
        for (int i = 0; i < 4; i++){
            int c = tid + i*256;
            int row = c >> 4, q4 = (c & 15) * 4;
            long go = (long)(t0+row)*DM + h*HDIM + q4;
            cp16((uint32_t)__cvta_generic_to_shared(&KH[row*68 + q4]), khg + go);
            cp16((uint32_t)__cvta_generic_to_shared(&KL[row*68 + q4]), klg + go);
        }
        const int rbase = s0 - t0 + 960;
        #pragma unroll
        for (int i = 0; i < 8; i++){
            int c = tid + i*256;              // need 127*16 = 2032
            if (c < 2032){
                int row = c >> 4, q4 = (c & 15) * 4;
                long go = (long)(rbase+row)*HDIM + q4;
                cp16((uint32_t)__cvta_generic_to_shared(&EH[row*68 + q4]), erh + go);
                cp16((uint32_t)__cvta_generic_to_shared(&EL[row*68 + q4]), erl + go);
            }
        }
        cp_commit();
    };
    auto issue_v = [&](int t0){
        #pragma unroll
        for (int i = 0; i < 4; i++){
            int c = tid + i*256;
            int row = c >> 4, q4 = (c & 15) * 4;
            long go = (long)(t0+row)*DM + h*HDIM + q4;
            cp16((uint32_t)__cvta_generic_to_shared(&VH[row*72 + q4]), vhg + go);
            cp16((uint32_t)__cvta_generic_to_shared(&VL[row*72 + q4]), vlg + go);
        }
        cp_commit();
    };

    float O[4][4] = {};
    float m0 = -1e30f, m1 = -1e30f, l0 = 0.f, l1 = 0.f;
    const int r0 = wm*16 + g, r1 = r0 + 8;

    issue_ke(0);

    for (int it = 0; it < 16; it++){
        // S1: KE(it) ready; V buffer free (all threads past PV(it-1))
        asm volatile("cp.async.wait_group 0;\n" ::: "memory");
        __syncthreads();
        issue_v(it*64);

        // ---- QK + QE mma (all operands pre-split)
        float accS[4][4] = {};
        float accR[2][4][4] = {};
        #pragma unroll
        for (int kk = 0; kk < 64; kk += 8){
            uint32_t ah0 = __float_as_uint(QH[r0*68 + kk + t]);
            uint32_t ah1 = __float_as_uint(QH[r1*68 + kk + t]);
            uint32_t ah2 = __float_as_uint(QH[r0*68 + kk + t + 4]);
            uint32_t ah3 = __float_as_uint(QH[r1*68 + kk + t + 4]);
            uint32_t al0 = __float_as_uint(QL[r0*68 + kk + t]);
            uint32_t al1 = __float_as_uint(QL[r1*68 + kk + t]);
            uint32_t al2 = __float_as_uint(QL[r0*68 + kk + t + 4]);
            uint32_t al3 = __float_as_uint(QL[r1*68 + kk + t + 4]);
            #pragma unroll
            for (int nt = 0; nt < 4; nt++){
                int bn = wn*32 + nt*8 + g;
                uint32_t bh0 = __float_as_uint(KH[bn*68 + kk + t]);
                uint32_t bh1 = __float_as_uint(KH[bn*68 + kk + t + 4]);
                uint32_t bl0 = __float_as_uint(KL[bn*68 + kk + t]);
                uint32_t bl1 = __float_as_uint(KL[bn*68 + kk + t + 4]);
                mma_tf32(accS[nt], ah0,ah1,ah2,ah3, bh0,bh1);
                mma_tf32(accS[nt], ah0,ah1,ah2,ah3, bl0,bl1);
                mma_tf32(accS[nt], al0,al1,al2,al3, bh0,bh1);
            }
            #pragma unroll
            for (int nh = 0; nh < 2; nh++)
            #pragma unroll
            for (int nt = 0; nt < 4; nt++){
                int bn = nh*64 + wn*32 + nt*8 + g;
                uint32_t bh0 = __float_as_uint(EH[bn*68 + kk + t]);
                uint32_t bh1 = __float_as_uint(EH[bn*68 + kk + t + 4]);
                uint32_t bl0 = __float_as_uint(EL[bn*68 + kk + t]);
                uint32_t bl1 = __float_as_uint(EL[bn*68 + kk + t + 4]);
                mma_tf32(accR[nh][nt], ah0,ah1,ah2,ah3, bh0,bh1);
                mma_tf32(accR[nh][nt], ah0,ah1,ah2,ah3, bl0,bl1);
                mma_tf32(accR[nh][nt], al0,al1,al2,al3, bh0,bh1);
            }
        }

        // ---- store R to smem, stride 136
        #pragma unroll
        for (int nh = 0; nh < 2; nh++)
        #pragma unroll
        for (int nt = 0; nt < 4; nt++){
            int u0 = nh*64 + wn*32 + nt*8 + 2*t;
            RS[r0*136 + u0    ] = accR[nh][nt][0];
            RS[r0*136 + u0 + 1] = accR[nh][nt][1];
            RS[r1*136 + u0    ] = accR[nh][nt][2];
            RS[r1*136 + u0 + 1] = accR[nh][nt][3];
        }
        __syncthreads();                                       // S2 (K,E consumed)
        if (it < 15) issue_ke((it+1)*64);

        // ---- logits; row max
        float tm0 = -1e30f, tm1 = -1e30f;
        #pragma unroll
        for (int nt = 0; nt < 4; nt++){
            #pragma unroll
            for (int j = 0; j < 2; j++){
                int tj = wn*32 + nt*8 + 2*t + j;
                float x0 = accS[nt][j]   * QK_SCALE + RS[r0*136 + (r0 - tj + 63)];
                float x1 = accS[nt][2+j] * QK_SCALE + RS[r1*136 + (r1 - tj + 63)];
                accS[nt][j]   = x0;
                accS[nt][2+j] = x1;
                tm0 = fmaxf(tm0, x0);
                tm1 = fmaxf(tm1, x1);
            }
        }
        tm0 = fmaxf(tm0, __shfl_xor_sync(0xffffffffu, tm0, 1));
        tm0 = fmaxf(tm0, __shfl_xor_sync(0xffffffffu, tm0, 2));
        tm1 = fmaxf(tm1, __shfl_xor_sync(0xffffffffu, tm1, 1));
        tm1 = fmaxf(tm1, __shfl_xor_sync(0xffffffffu, tm1, 2));
        if (t == 0){ redm[wn*64 + r0] = tm0; redm[wn*64 + r1] = tm1; }
        __syncthreads();                                       // S3

        float M0 = fmaxf(m0, fmaxf(redm[r0], redm[64 + r0]));
        float M1 = fmaxf(m1, fmaxf(redm[r1], redm[64 + r1]));

        // ---- exp, partial sums; write P pre-split (aliases R region)
        float sum0 = 0.f, sum1 = 0.f;
        #pragma unroll
        for (int nt = 0; nt < 4; nt++){
            #pragma unroll
            for (int j = 0; j < 2; j++){
                int tj = wn*32 + nt*8 + 2*t + j;
                float p0 = __expf(accS[nt][j]   - M0);
                float p1 = __expf(accS[nt][2+j] - M1);
                sum0 += p0; sum1 += p1;
                uint32_t hh, ll;
                split_tf(p0, hh, ll);
                PH[r0*68 + tj] = __uint_as_float(hh);
                PL[r0*68 + tj] = __uint_as_float(ll);
                split_tf(p1, hh, ll);
                PH[r1*68 + tj] = __uint_as_float(hh);
                PL[r1*68 + tj] = __uint_as_float(ll);
            }
        }
        sum0 += __shfl_xor_sync(0xffffffffu, sum0, 1);
        sum0 += __shfl_xor_sync(0xffffffffu, sum0, 2);
        sum1 += __shfl_xor_sync(0xffffffffu, sum1, 1);
        sum1 += __shfl_xor_sync(0xffffffffu, sum1, 2);
        if (t == 0){ reds[wn*64 + r0] = sum0; reds[wn*64 + r1] = sum1; }

        float f0 = __expf(m0 - M0), f1 = __expf(m1 - M1);
        #pragma unroll
        for (int nt = 0; nt < 4; nt++){
            O[nt][0] *= f0; O[nt][1] *= f0;
            O[nt][2] *= f1; O[nt][3] *= f1;
        }

        // wait V(it): pending groups = [V(it), KE(it+1)] or [V(15)]
        if (it < 15) asm volatile("cp.async.wait_group 1;\n" ::: "memory");
        else         asm volatile("cp.async.wait_group 0;\n" ::: "memory");
        __syncthreads();                                       // S4

        l0 = l0*f0 + reds[r0] + reds[64 + r0];
        l1 = l1*f1 + reds[r1] + reds[64 + r1];
        m0 = M0; m1 = M1;

        // ---- O += P @ V (both pre-split)
        #pragma unroll
        for (int kk = 0; kk < 64; kk += 8){
            uint32_t ah0 = __float_as_uint(PH[r0*68 + kk + t]);
            uint32_t ah1 = __float_as_uint(PH[r1*68 + kk + t]);
            uint32_t ah2 = __float_as_uint(PH[r0*68 + kk + t + 4]);
            uint32_t ah3 = __float_as_uint(PH[r1*68 + kk + t + 4]);
            uint32_t al0 = __float_as_uint(PL[r0*68 + kk + t]);
            uint32_t al1 = __float_as_uint(PL[r1*68 + kk + t]);
            uint32_t al2 = __float_as_uint(PL[r0*68 + kk + t + 4]);
            uint32_t al3 = __float_as_uint(PL[r1*68 + kk + t + 4]);
            #pragma unroll
            for (int nt = 0; nt < 4; nt++){
                int bn = wn*32 + nt*8 + g;
                uint32_t bh0 = __float_as_uint(VH[(kk + t    )*72 + bn]);
                uint32_t bh1 = __float_as_uint(VH[(kk + t + 4)*72 + bn]);
                uint32_t bl0 = __float_as_uint(VL[(kk + t    )*72 + bn]);
                uint32_t bl1 = __float_as_uint(VL[(kk + t + 4)*72 + bn]);
                mma_tf32(O[nt], ah0,ah1,ah2,ah3, bh0,bh1);
                mma_tf32(O[nt], ah0,ah1,ah2,ah3, bl0,bl1);
                mma_tf32(O[nt], al0,al1,al2,al3, bh0,bh1);
            }
        }
    }

    // ---- epilogue
    const float il0 = 1.f / l0, il1 = 1.f / l1;
    const int gr0 = s0 + r0, gr1 = s0 + r1;
    #pragma unroll
    for (int nt = 0; nt < 4; nt++){
        #pragma unroll
        for (int j = 0; j < 2; j++){
            int dc = h*HDIM + wn*32 + nt*8 + 2*t + j;
            ao[(long)gr0*DM + dc] = O[nt][j]   * il0;
            ao[(long)gr1*DM + dc] = O[nt][2+j] * il1;
        }
    }
}

// ---------------------------------------------------------------------------
// Host orchestration
// ---------------------------------------------------------------------------
extern "C" void kernel_launch(void* const* d_in, const int* in_sizes, int n_in,
                              void* d_out, int out_size)
{
    const float* x     = (const float*)d_in[0];
    const float* emb_W = (const float*)d_in[1];
    const float* emb_b = (const float*)d_in[2];
    const float* Wq    = (const float*)d_in[3];
    const float* bq    = (const float*)d_in[4];
    const float* Wk    = (const float*)d_in[5];
    const float* bk    = (const float*)d_in[6];
    const float* Wv    = (const float*)d_in[7];
    const float* bv    = (const float*)d_in[8];
    const float* Wo    = (const float*)d_in[9];
    const float* bo    = (const float*)d_in[10];
    const float* Er    = (const float*)d_in[11];
    const float* ln1g  = (const float*)d_in[12];
    const float* ln1b  = (const float*)d_in[13];
    const float* W1    = (const float*)d_in[14];
    const float* b1    = (const float*)d_in[15];
    const float* W2    = (const float*)d_in[16];
    const float* b2    = (const float*)d_in[17];
    const float* ln2g  = (const float*)d_in[18];
    const float* ln2b  = (const float*)d_in[19];
    const float* lnfg  = (const float*)d_in[20];
    const float* lnfb  = (const float*)d_in[21];
    const float* Wi    = (const float*)d_in[22];
    const float* bi    = (const float*)d_in[23];
    const float* Wf    = (const float*)d_in[24];
    const float* bf    = (const float*)d_in[25];
    float* out = (float*)d_out;

    float *h, *n, *q, *kh, *kl, *vh, *vl, *ao, *f1, *fi, *wh, *wl, *erh, *erl;
    cudaGetSymbolAddress((void**)&h,  g_h);
    cudaGetSymbolAddress((void**)&n,  g_n);
    cudaGetSymbolAddress((void**)&q,  g_q);
    cudaGetSymbolAddress((void**)&kh, g_kh);
    cudaGetSymbolAddress((void**)&kl, g_kl);
    cudaGetSymbolAddress((void**)&vh, g_vh);
    cudaGetSymbolAddress((void**)&vl, g_vl);
    cudaGetSymbolAddress((void**)&ao, g_ao);
    cudaGetSymbolAddress((void**)&f1, g_f1);
    cudaGetSymbolAddress((void**)&fi, g_fi);
    cudaGetSymbolAddress((void**)&wh, g_wh);
    cudaGetSymbolAddress((void**)&wl, g_wl);
    cudaGetSymbolAddress((void**)&erh, g_erh);
    cudaGetSymbolAddress((void**)&erl, g_erl);

    cudaFuncSetAttribute(attn_k, cudaFuncAttributeMaxDynamicSharedMemorySize, ATT_SMEM);

    // ---- one fused weight pre-split launch
    {
        WsegArgs a;
        const float* srcs[NSEG] = {emb_W, Wq, Wk, Wv, Wo, W1, W2, Wi, Wf, Er};
        long offs[NSEG] = {OFF_EMB, OFF_WQ, OFF_WK, OFF_WV, OFF_WO,
                           OFF_W1, OFF_W2, OFF_WI, OFF_WF, -1};
        int nfl[NSEG] = {65536, NLAY*DM*DM, NLAY*DM*DM, NLAY*DM*DM, NLAY*DM*DM,
                         NLAY*DM*2048, NLAY*2048*DM, DM*1024, 1024*390,
                         NLAY*2047*HDIM};
        for (int i = 0; i < NSEG; i++){
            a.src[i] = (const float4*)srcs[i];
            a.n4[i]  = nfl[i] >> 2;
            if (offs[i] >= 0){
                a.dh[i] = (float4*)(wh + offs[i]);
                a.dl[i] = (float4*)(wl + offs[i]);
            } else {
                a.dh[i] = (float4*)erh;
                a.dl[i] = (float4*)erl;
            }
        }
        wsplit_all_k<<<dim3(4096, NSEG), 256>>>(a);
    }

    // embed: h = x @ emb_W + emb_b
    gemm_tc<0><<<dim3(8,16), 256>>>(x,128, wh+OFF_EMB, wl+OFF_EMB,512,
                                    h,512, emb_b, nullptr, SQ, DM, 128);

    for (int l = 0; l < NLAY; l++) {
        const long lw  = (long)l*DM*DM;
        const long lw1 = (long)l*DM*2048;

        ln_k<<<SQ,128>>>(h, ln1g + l*DM, ln1b + l*DM, n);

        gemm_qkv<<<dim3(8,16,3),256>>>(n, wh+OFF_WQ+lw, wl+OFF_WQ+lw,
                                       bq + l*DM, bk + l*DM, bv + l*DM,
                                       q, kh, kl, vh, vl);

        attn_k<<<dim3(16,NH),256,ATT_SMEM>>>(q, kh, kl, vh, vl,
                                             erh + (long)l*2047*HDIM,
                                             erl + (long)l*2047*HDIM, ao);

        gemm_tc<2><<<dim3(8,16),256>>>(ao,DM, wh+OFF_WO+lw, wl+OFF_WO+lw,DM,
                                       h,DM, bo + l*DM, h, SQ, DM, DM);

        ln_k<<<SQ,128>>>(h, ln2g + l*DM, ln2b + l*DM, n);

        gemm_tc<1><<<dim3(32,16),256>>>(n,DM, wh+OFF_W1+lw1, wl+OFF_W1+lw1,2048,
                                        f1,2048, b1 + l*2048, nullptr, SQ, 2048, DM);

        gemm_tc<2><<<dim3(8,16),256>>>(f1,2048, wh+OFF_W2+lw1, wl+OFF_W2+lw1,DM,
                                       h,DM, b2 + l*DM, h, SQ, DM, 2048);
    }

    ln_k<<<SQ,128>>>(h, lnfg, lnfb, n);
    gemm_tc<1><<<dim3(16,16),256>>>(n,DM, wh+OFF_WI, wl+OFF_WI,1024,
                                    fi,1024, bi, nullptr, SQ, 1024, DM);
    gemm_tc<0><<<dim3(7,16),256>>>(fi,1024, wh+OFF_WF, wl+OFF_WF,390,
                                   out,390, bf, nullptr, SQ, 390, 1024);
}